// round 5
// baseline (speedup 1.0000x reference)
#include <cuda_runtime.h>
#include <cuda_bf16.h>
#include <math.h>

typedef unsigned long long u64;

__device__ __forceinline__ u64 pack2(float x, float y) {
  u64 r; asm("mov.b64 %0,{%1,%2};" : "=l"(r) : "f"(x), "f"(y)); return r;
}
__device__ __forceinline__ u64 fma2(u64 a, u64 b, u64 c) {
  u64 d; asm("fma.rn.f32x2 %0,%1,%2,%3;" : "=l"(d) : "l"(a), "l"(b), "l"(c)); return d;
}
__device__ __forceinline__ float2 unpack2(u64 v) {
  float2 f; asm("mov.b64 {%0,%1},%2;" : "=f"(f.x), "=f"(f.y) : "l"(v)); return f;
}

// ---------------- scratch (device globals; no cudaMalloc allowed) ----------
__device__ float g_off [8 * 128 * 4096];   // offset features (after 1x1 conv)
__device__ float g_om  [8 * 216 * 4096];   // 3x3 conv output (off_y/off_x/mask raw)
__device__ float g_fsn [8 * 1024 * 128];   // feat_s transposed to [b][sp][c] (NHWC)
__device__ float g_align[8 * 64 * 4096];   // DCN output after relu
__device__ float g_wdt [288 * 64 * 4];     // W_dcn repacked: [(e>>2)][o][e&3], e = k*128+cc
__device__ float g_womt[128 * 9 * 216];    // W_om repacked: [(c*9+t)][o]
__device__ float g_wt_fsm[128 * 128];      // W_fsm^T : [c][o]
__device__ float g_wt_off[256 * 128];      // W_off^T : [c][o]
__device__ float g_wt_cat[64 * 128];       // W_cat^T : [c][o]

// ---------------- prep: transposes / repacks --------------------------------
__global__ void __launch_bounds__(256) k_prep(
    const float* __restrict__ fs, const float* __restrict__ W_fsm,
    const float* __restrict__ W_off, const float* __restrict__ W_cat,
    const float* __restrict__ W_om, const float* __restrict__ W_dcn) {
  int i = blockIdx.x * 256 + threadIdx.x;   // grid covers 1048576
  if (i < 1048576) {   // feat_s NCHW -> [b][sp][c]
    int b = i >> 17; int r = i & 131071; int c = r >> 10; int sp = r & 1023;
    g_fsn[((b << 10) + sp) * 128 + c] = fs[i];
  }
  if (i < 16384) g_wt_fsm[(i & 127) * 128 + (i >> 7)] = W_fsm[i];   // i = o*128+c
  if (i < 32768) g_wt_off[(i & 255) * 128 + (i >> 8)] = W_off[i];   // i = o*256+c
  if (i < 8192)  g_wt_cat[(i & 63)  * 128 + (i >> 6)] = W_cat[i];   // i = o*64+c
  if (i < 248832) {            // W_om: i = o*1152 + (c*9+t)
    int o = i / 1152; int r = i - o * 1152;
    g_womt[r * 216 + o] = W_om[i];
  }
  if (i < 73728) {             // W_dcn: i = o*1152 + cc*9 + k
    int o = i / 1152; int r = i - o * 1152; int cc = r / 9; int k = r - cc * 9;
    int e = k * 128 + cc;
    g_wdt[(e >> 2) * 256 + o * 4 + (e & 3)] = W_dcn[i];
  }
}

// ---------------- 1x1 conv + BN + relu : feat_arm (f32x2 over pixel pairs) --
__global__ void __launch_bounds__(256) k_fsm(
    const float* __restrict__ x, const float* __restrict__ s,
    const float* __restrict__ bias, float* __restrict__ arm) {
  __shared__ float xs[128 * 64];            // 32 KB input tile
  int b = blockIdx.x >> 6;
  int pbase = (blockIdx.x & 63) * 64;
  const float* xb = x + ((size_t)b * 128) * 4096 + pbase;
  for (int i = threadIdx.x; i < 128 * 64; i += 256)
    xs[i] = xb[(size_t)(i >> 6) * 4096 + (i & 63)];
  __syncthreads();
  int o  = threadIdx.x & 127;
  int ph = threadIdx.x >> 7;                // pixel half: 32 px each
  u64 acc[16];
#pragma unroll
  for (int p = 0; p < 16; p++) acc[p] = 0ull;
  for (int c = 0; c < 128; c++) {
    float w = g_wt_fsm[c * 128 + o];
    u64 wd = pack2(w, w);
    const ulonglong2* xr = (const ulonglong2*)(xs + c * 64 + ph * 32);
#pragma unroll
    for (int q = 0; q < 8; q++) {
      ulonglong2 v = xr[q];
      acc[2*q+0] = fma2(wd, v.x, acc[2*q+0]);
      acc[2*q+1] = fma2(wd, v.y, acc[2*q+1]);
    }
  }
  float sc = s[o], bi = bias[o];
  float* op = arm + ((size_t)(b * 128 + o)) * 4096 + pbase + ph * 32;
#pragma unroll
  for (int q = 0; q < 16; q++) {
    float2 f = unpack2(acc[q]);
    op[2*q+0] = fmaxf(fmaf(f.x, sc, bi), 0.f);
    op[2*q+1] = fmaxf(fmaf(f.y, sc, bi), 0.f);
  }
}

// ------------- 1x1 conv over concat(arm, 2*upsample(feat_s)) (f32x2) --------
__global__ void __launch_bounds__(256) k_off(
    const float* __restrict__ arm, const float* __restrict__ fs,
    const float* __restrict__ s, const float* __restrict__ bias) {
  __shared__ float xs1[128 * 32];
  __shared__ float xs2[128 * 32];
  int bid = blockIdx.x;                      // 1024 blocks
  int b = bid >> 7; int rem = bid & 127;
  int h = rem >> 1; int wb = (rem & 1) << 5;
  for (int i = threadIdx.x; i < 4096; i += 256) {
    int c = i >> 5; int p = i & 31;
    xs1[i] = arm[((size_t)(b * 128 + c)) * 4096 + h * 64 + wb + p];
    xs2[i] = 2.0f * fs[((size_t)(b * 128 + c)) * 1024 + (h >> 1) * 32 + ((wb + p) >> 1)];
  }
  __syncthreads();
  int o  = threadIdx.x & 127;
  int ph = threadIdx.x >> 7;                 // 16 px each
  u64 acc[8];
#pragma unroll
  for (int p = 0; p < 8; p++) acc[p] = 0ull;
  for (int c = 0; c < 128; c++) {
    float w = g_wt_off[c * 128 + o];
    u64 wd = pack2(w, w);
    const ulonglong2* xr = (const ulonglong2*)(xs1 + c * 32 + ph * 16);
#pragma unroll
    for (int q = 0; q < 4; q++) {
      ulonglong2 v = xr[q];
      acc[2*q+0] = fma2(wd, v.x, acc[2*q+0]);
      acc[2*q+1] = fma2(wd, v.y, acc[2*q+1]);
    }
  }
  for (int c = 0; c < 128; c++) {
    float w = g_wt_off[(128 + c) * 128 + o];
    u64 wd = pack2(w, w);
    const ulonglong2* xr = (const ulonglong2*)(xs2 + c * 32 + ph * 16);
#pragma unroll
    for (int q = 0; q < 4; q++) {
      ulonglong2 v = xr[q];
      acc[2*q+0] = fma2(wd, v.x, acc[2*q+0]);
      acc[2*q+1] = fma2(wd, v.y, acc[2*q+1]);
    }
  }
  float sc = s[o], bi = bias[o];
  float* op = g_off + ((size_t)(b * 128 + o)) * 4096 + h * 64 + wb + ph * 16;
#pragma unroll
  for (int q = 0; q < 8; q++) {
    float2 f = unpack2(acc[q]);
    op[2*q+0] = fmaxf(fmaf(f.x, sc, bi), 0.f);
    op[2*q+1] = fmaxf(fmaf(f.y, sc, bi), 0.f);
  }
}

// ------- 3x3 conv: offset/mask (216 ch), f32x2 o-pairs, 32-px tiles ---------
// Block: 224 threads, t<216 compute (o-pair, px-half of 16). Channels chunked
// by 32 through a 26 KB duplicated halo buffer. 1024 blocks.
__global__ void __launch_bounds__(224, 3) k_om(const float* __restrict__ b_om) {
  __shared__ u64 xs[32 * 102];               // [c][3 kh][34 cols] dup, 26112 B
  int bid = blockIdx.x;                      // 1024 = b(8) x h(64) x wq(2)
  int b = bid >> 7; int rem = bid & 127;
  int h = rem >> 1; int wb = (rem & 1) << 5;
  int t = threadIdx.x;
  int op2 = t >> 1;                          // output pair 0..107
  int ph  = t & 1;                           // pixel half (16 px)
  u64 acc[16];
#pragma unroll
  for (int p = 0; p < 16; p++) acc[p] = 0ull;
  const float* wbase = g_womt + op2 * 2;

  for (int cb = 0; cb < 4; cb++) {
    for (int i = t; i < 32 * 102; i += 224) {
      int c = i / 102; int r = i - c * 102; int kh = r / 34; int col = r - kh * 34;
      int hh = h + kh - 1; int ww = wb + col - 1;
      float v = 0.f;
      if ((unsigned)hh < 64u && (unsigned)ww < 64u)
        v = g_off[((size_t)(b * 128 + cb * 32 + c)) * 4096 + hh * 64 + ww];
      xs[i] = pack2(v, v);
    }
    __syncthreads();
    if (t < 216) {
      for (int c = 0; c < 32; c++) {
        const float* wc = wbase + ((cb * 32 + c) * 9) * 216;
        const u64* xc = xs + c * 102 + ph * 16;
#pragma unroll
        for (int kh = 0; kh < 3; kh++) {
          u64 w0 = *(const u64*)(wc + (kh * 3 + 0) * 216);
          u64 w1 = *(const u64*)(wc + (kh * 3 + 1) * 216);
          u64 w2 = *(const u64*)(wc + (kh * 3 + 2) * 216);
          const u64* xr = xc + kh * 34;
          u64 a0 = xr[0], a1 = xr[1];
#pragma unroll
          for (int j = 0; j < 16; j++) {
            u64 a2 = xr[j + 2];
            acc[j] = fma2(w0, a0, acc[j]);
            acc[j] = fma2(w1, a1, acc[j]);
            acc[j] = fma2(w2, a2, acc[j]);
            a0 = a1; a1 = a2;
          }
        }
      }
    }
    __syncthreads();
  }
  if (t < 216) {
    int o0 = op2 * 2;
    float bo0 = b_om[o0], bo1 = b_om[o0 + 1];
    float* p0 = g_om + ((size_t)(b * 216 + o0)) * 4096 + h * 64 + wb + ph * 16;
    float* p1 = p0 + 4096;
#pragma unroll
    for (int j = 0; j < 16; j++) {
      float2 f = unpack2(acc[j]);
      p0[j] = f.x + bo0;
      p1[j] = f.y + bo1;
    }
  }
}

// ---------------- modulated deformable conv + relu (R2 version) -------------
__global__ void __launch_bounds__(256) k_dcn(const float* __restrict__ b_dcn) {
  extern __shared__ float sm[];
  float* pw   = sm;                       // [16 px][72 gk][4 corners] weights
  int*   pidx = (int*)(sm + 4608);        // matching channel-base offsets
  float* val  = sm + 9216;                // [16 px][1152 e], e = k*128 + cc
  int bid = blockIdx.x;                   // 2048 blocks
  int b = bid >> 8; int rem = bid & 255;
  int h = rem >> 2; int wb = (rem & 3) << 4;
  const float* omb = g_om + (size_t)b * 216 * 4096 + h * 64 + wb;

  // phase 0: per-(pixel,g,k) bilinear params (mask folded into weights)
  for (int i = threadIdx.x; i < 1152; i += 256) {
    int p = i / 72; int r = i - p * 72; int g = r / 9; int k = r - g * 9;
    int wq = wb + p;
    float oy = omb[(g * 9 + k) * 4096 + p];
    float ox = omb[(72 + g * 9 + k) * 4096 + p];
    float mr = omb[(144 + g * 9 + k) * 4096 + p];
    float m = 1.0f / (1.0f + expf(-mr));
    float py = (float)(h + k / 3 - 1) + oy;
    float px = (float)(wq + k % 3 - 1) + ox;
    float y0 = floorf(py), x0 = floorf(px);
    float ty = py - y0, tx = px - x0;
    int iy0 = (int)y0, ix0 = (int)x0;
#pragma unroll
    for (int j = 0; j < 4; j++) {
      int iy = iy0 + (j >> 1), ix = ix0 + (j & 1);
      bool v = (iy >= 0) && (iy < 64) && (ix >= 0) && (ix < 64);
      float wy = (j >> 1) ? ty : 1.0f - ty;
      float wx = (j & 1) ? tx : 1.0f - tx;
      pw[i * 4 + j]   = v ? wy * wx * m : 0.0f;
      pidx[i * 4 + j] = v ? (((iy >> 1) * 32 + (ix >> 1)) * 128) : 0;
    }
  }
  __syncthreads();

  // phase 1: bilinear gathers from NHWC feat_s -> val, float4 over channels
  const float* fsb = g_fsn + (size_t)b * 1024 * 128;
  for (int ei = threadIdx.x; ei < 4608; ei += 256) {
    int p = ei / 288; int r = ei - p * 288;
    int k = r >> 5; int cc4 = r & 31; int g = cc4 >> 2;
    int slot = (p * 72 + g * 9 + k) * 4;
    float4 a = make_float4(0.f, 0.f, 0.f, 0.f);
#pragma unroll
    for (int j = 0; j < 4; j++) {
      float w = pw[slot + j];
      const float4 v = *(const float4*)(fsb + pidx[slot + j] + cc4 * 4);
      a.x = fmaf(w, v.x, a.x);
      a.y = fmaf(w, v.y, a.y);
      a.z = fmaf(w, v.z, a.z);
      a.w = fmaf(w, v.w, a.w);
    }
    *(float4*)(val + p * 1152 + k * 128 + cc4 * 4) = a;
  }
  __syncthreads();

  // phase 2: out[o] = relu(b + sum_e Wdcn_t[e][o] * val[p][e]), 4 px/thread
  int o  = threadIdx.x & 63;
  int ps = threadIdx.x >> 6;
  const float4* w4 = (const float4*)g_wdt;        // [288][64] of float4
  const float4* v0 = (const float4*)(val + (ps * 4 + 0) * 1152);
  const float4* v1 = (const float4*)(val + (ps * 4 + 1) * 1152);
  const float4* v2 = (const float4*)(val + (ps * 4 + 2) * 1152);
  const float4* v3 = (const float4*)(val + (ps * 4 + 3) * 1152);
  float a0 = 0.f, a1 = 0.f, a2 = 0.f, a3 = 0.f;
  for (int eq = 0; eq < 288; eq++) {
    float4 w = w4[eq * 64 + o];
    float4 x0 = v0[eq], x1 = v1[eq], x2 = v2[eq], x3 = v3[eq];
    a0 = fmaf(w.x, x0.x, a0); a0 = fmaf(w.y, x0.y, a0);
    a0 = fmaf(w.z, x0.z, a0); a0 = fmaf(w.w, x0.w, a0);
    a1 = fmaf(w.x, x1.x, a1); a1 = fmaf(w.y, x1.y, a1);
    a1 = fmaf(w.z, x1.z, a1); a1 = fmaf(w.w, x1.w, a1);
    a2 = fmaf(w.x, x2.x, a2); a2 = fmaf(w.y, x2.y, a2);
    a2 = fmaf(w.z, x2.z, a2); a2 = fmaf(w.w, x2.w, a2);
    a3 = fmaf(w.x, x3.x, a3); a3 = fmaf(w.y, x3.y, a3);
    a3 = fmaf(w.z, x3.z, a3); a3 = fmaf(w.w, x3.w, a3);
  }
  float bo = b_dcn[o];
  float4 r;
  r.x = fmaxf(a0 + bo, 0.f);
  r.y = fmaxf(a1 + bo, 0.f);
  r.z = fmaxf(a2 + bo, 0.f);
  r.w = fmaxf(a3 + bo, 0.f);
  *(float4*)(g_align + ((size_t)(b * 64 + o)) * 4096 + h * 64 + wb + ps * 4) = r;
}

// ---------------- final 1x1 conv + BN + relu + residual (f32x2) -------------
__global__ void __launch_bounds__(256) k_cat(
    const float* __restrict__ s, const float* __restrict__ bias,
    const float* __restrict__ arm, float* __restrict__ out) {
  __shared__ float xs[64 * 64];              // 16 KB
  int b = blockIdx.x >> 6;
  int pbase = (blockIdx.x & 63) * 64;
  for (int i = threadIdx.x; i < 4096; i += 256)
    xs[i] = g_align[((size_t)(b * 64 + (i >> 6))) * 4096 + pbase + (i & 63)];
  __syncthreads();
  int o  = threadIdx.x & 127;
  int ph = threadIdx.x >> 7;
  u64 acc[16];
#pragma unroll
  for (int p = 0; p < 16; p++) acc[p] = 0ull;
  for (int c = 0; c < 64; c++) {
    float w = g_wt_cat[c * 128 + o];
    u64 wd = pack2(w, w);
    const ulonglong2* xr = (const ulonglong2*)(xs + c * 64 + ph * 32);
#pragma unroll
    for (int q = 0; q < 8; q++) {
      ulonglong2 v = xr[q];
      acc[2*q+0] = fma2(wd, v.x, acc[2*q+0]);
      acc[2*q+1] = fma2(wd, v.y, acc[2*q+1]);
    }
  }
  float sc = s[o], bi = bias[o];
  size_t base = ((size_t)(b * 128 + o)) * 4096 + pbase + ph * 32;
#pragma unroll
  for (int q = 0; q < 16; q++) {
    float2 f = unpack2(acc[q]);
    out[base + 2*q+0] = fmaxf(fmaf(f.x, sc, bi), 0.f) + arm[base + 2*q+0];
    out[base + 2*q+1] = fmaxf(fmaf(f.y, sc, bi), 0.f) + arm[base + 2*q+1];
  }
}

// ---------------- launcher ---------------------------------------------------
extern "C" void kernel_launch(void* const* d_in, const int* in_sizes, int n_in,
                              void* d_out, int out_size) {
  const float* feat_l = (const float*)d_in[0];
  const float* feat_s = (const float*)d_in[1];
  const float* W_fsm  = (const float*)d_in[2];
  const float* s_fsm  = (const float*)d_in[3];
  const float* b_fsm  = (const float*)d_in[4];
  const float* W_off  = (const float*)d_in[5];
  const float* s_off  = (const float*)d_in[6];
  const float* b_off  = (const float*)d_in[7];
  const float* W_om   = (const float*)d_in[8];
  const float* b_om   = (const float*)d_in[9];
  const float* W_dcn  = (const float*)d_in[10];
  const float* b_dcn  = (const float*)d_in[11];
  const float* W_cat  = (const float*)d_in[12];
  const float* s_cat  = (const float*)d_in[13];
  const float* b_cat  = (const float*)d_in[14];

  float* out_feat = (float*)d_out;
  float* out_arm  = out_feat + (size_t)8 * 128 * 4096;   // second tuple element

  cudaFuncSetAttribute(k_dcn, cudaFuncAttributeMaxDynamicSharedMemorySize, 110592);

  k_prep<<<4096, 256>>>(feat_s, W_fsm, W_off, W_cat, W_om, W_dcn);
  k_fsm <<<512, 256>>>(feat_l, s_fsm, b_fsm, out_arm);
  k_off <<<1024, 256>>>(out_arm, feat_s, s_off, b_off);
  k_om  <<<1024, 224>>>(b_om);
  k_dcn <<<2048, 256, 110592>>>(b_dcn);
  k_cat <<<512, 256>>>(s_cat, b_cat, out_arm, out_feat);
}

// round 6
// speedup vs baseline: 1.0002x; 1.0002x over previous
#include <cuda_runtime.h>
#include <cuda_bf16.h>
#include <math.h>

typedef unsigned long long u64;

__device__ __forceinline__ u64 pack2(float x, float y) {
  u64 r; asm("mov.b64 %0,{%1,%2};" : "=l"(r) : "f"(x), "f"(y)); return r;
}
__device__ __forceinline__ u64 fma2(u64 a, u64 b, u64 c) {
  u64 d; asm("fma.rn.f32x2 %0,%1,%2,%3;" : "=l"(d) : "l"(a), "l"(b), "l"(c)); return d;
}
__device__ __forceinline__ float2 unpack2(u64 v) {
  float2 f; asm("mov.b64 {%0,%1},%2;" : "=f"(f.x), "=f"(f.y) : "l"(v)); return f;
}

// ---------------- scratch (device globals; no cudaMalloc allowed) ----------
__device__ float g_off [8 * 128 * 4096];   // offset features (after 1x1 conv)
__device__ float g_om  [8 * 216 * 4096];   // 3x3 conv output (off_y/off_x/mask raw)
__device__ float g_fsn [8 * 1024 * 128];   // feat_s transposed to [b][sp][c] (NHWC)
__device__ float g_align[8 * 64 * 4096];   // DCN output after relu
__device__ float g_wdt [288 * 64 * 4];     // W_dcn repacked: [(e>>2)][o][e&3], e = k*128+cc
__device__ float g_womt[128 * 9 * 216];    // W_om repacked: [(c*9+t)][o]
__device__ float g_wt_fsm[128 * 128];      // W_fsm^T : [c][o]
__device__ float g_wt_off[256 * 128];      // W_off^T : [c][o]
__device__ float g_wt_cat[64 * 128];       // W_cat^T : [c][o]

// ---------------- prep: transposes / repacks --------------------------------
__global__ void __launch_bounds__(256) k_prep(
    const float* __restrict__ fs, const float* __restrict__ W_fsm,
    const float* __restrict__ W_off, const float* __restrict__ W_cat,
    const float* __restrict__ W_om, const float* __restrict__ W_dcn) {
  int i = blockIdx.x * 256 + threadIdx.x;   // grid covers 1048576
  if (i < 1048576) {   // feat_s NCHW -> [b][sp][c]
    int b = i >> 17; int r = i & 131071; int c = r >> 10; int sp = r & 1023;
    g_fsn[((b << 10) + sp) * 128 + c] = fs[i];
  }
  if (i < 16384) g_wt_fsm[(i & 127) * 128 + (i >> 7)] = W_fsm[i];   // i = o*128+c
  if (i < 32768) g_wt_off[(i & 255) * 128 + (i >> 8)] = W_off[i];   // i = o*256+c
  if (i < 8192)  g_wt_cat[(i & 63)  * 128 + (i >> 6)] = W_cat[i];   // i = o*64+c
  if (i < 248832) {            // W_om: i = o*1152 + (c*9+t)
    int o = i / 1152; int r = i - o * 1152;
    g_womt[r * 216 + o] = W_om[i];
  }
  if (i < 73728) {             // W_dcn: i = o*1152 + cc*9 + k
    int o = i / 1152; int r = i - o * 1152; int cc = r / 9; int k = r - cc * 9;
    int e = k * 128 + cc;
    g_wdt[(e >> 2) * 256 + o * 4 + (e & 3)] = W_dcn[i];
  }
}

// ---------------- 1x1 conv + BN + relu : feat_arm (f32x2 over pixel pairs) --
__global__ void __launch_bounds__(256) k_fsm(
    const float* __restrict__ x, const float* __restrict__ s,
    const float* __restrict__ bias, float* __restrict__ arm) {
  __shared__ float xs[128 * 64];            // 32 KB input tile
  int b = blockIdx.x >> 6;
  int pbase = (blockIdx.x & 63) * 64;
  const float* xb = x + ((size_t)b * 128) * 4096 + pbase;
  for (int i = threadIdx.x; i < 128 * 64; i += 256)
    xs[i] = xb[(size_t)(i >> 6) * 4096 + (i & 63)];
  __syncthreads();
  int o  = threadIdx.x & 127;
  int ph = threadIdx.x >> 7;                // pixel half: 32 px each
  u64 acc[16];
#pragma unroll
  for (int p = 0; p < 16; p++) acc[p] = 0ull;
  for (int c = 0; c < 128; c++) {
    float w = g_wt_fsm[c * 128 + o];
    u64 wd = pack2(w, w);
    const ulonglong2* xr = (const ulonglong2*)(xs + c * 64 + ph * 32);
#pragma unroll
    for (int q = 0; q < 8; q++) {
      ulonglong2 v = xr[q];
      acc[2*q+0] = fma2(wd, v.x, acc[2*q+0]);
      acc[2*q+1] = fma2(wd, v.y, acc[2*q+1]);
    }
  }
  float sc = s[o], bi = bias[o];
  float* op = arm + ((size_t)(b * 128 + o)) * 4096 + pbase + ph * 32;
#pragma unroll
  for (int q = 0; q < 16; q++) {
    float2 f = unpack2(acc[q]);
    op[2*q+0] = fmaxf(fmaf(f.x, sc, bi), 0.f);
    op[2*q+1] = fmaxf(fmaf(f.y, sc, bi), 0.f);
  }
}

// ------------- 1x1 conv over concat(arm, 2*upsample(feat_s)) (f32x2) --------
__global__ void __launch_bounds__(256) k_off(
    const float* __restrict__ arm, const float* __restrict__ fs,
    const float* __restrict__ s, const float* __restrict__ bias) {
  __shared__ float xs1[128 * 32];
  __shared__ float xs2[128 * 32];
  int bid = blockIdx.x;                      // 1024 blocks
  int b = bid >> 7; int rem = bid & 127;
  int h = rem >> 1; int wb = (rem & 1) << 5;
  for (int i = threadIdx.x; i < 4096; i += 256) {
    int c = i >> 5; int p = i & 31;
    xs1[i] = arm[((size_t)(b * 128 + c)) * 4096 + h * 64 + wb + p];
    xs2[i] = 2.0f * fs[((size_t)(b * 128 + c)) * 1024 + (h >> 1) * 32 + ((wb + p) >> 1)];
  }
  __syncthreads();
  int o  = threadIdx.x & 127;
  int ph = threadIdx.x >> 7;                 // 16 px each
  u64 acc[8];
#pragma unroll
  for (int p = 0; p < 8; p++) acc[p] = 0ull;
  for (int c = 0; c < 128; c++) {
    float w = g_wt_off[c * 128 + o];
    u64 wd = pack2(w, w);
    const ulonglong2* xr = (const ulonglong2*)(xs1 + c * 32 + ph * 16);
#pragma unroll
    for (int q = 0; q < 4; q++) {
      ulonglong2 v = xr[q];
      acc[2*q+0] = fma2(wd, v.x, acc[2*q+0]);
      acc[2*q+1] = fma2(wd, v.y, acc[2*q+1]);
    }
  }
  for (int c = 0; c < 128; c++) {
    float w = g_wt_off[(128 + c) * 128 + o];
    u64 wd = pack2(w, w);
    const ulonglong2* xr = (const ulonglong2*)(xs2 + c * 32 + ph * 16);
#pragma unroll
    for (int q = 0; q < 4; q++) {
      ulonglong2 v = xr[q];
      acc[2*q+0] = fma2(wd, v.x, acc[2*q+0]);
      acc[2*q+1] = fma2(wd, v.y, acc[2*q+1]);
    }
  }
  float sc = s[o], bi = bias[o];
  float* op = g_off + ((size_t)(b * 128 + o)) * 4096 + h * 64 + wb + ph * 16;
#pragma unroll
  for (int q = 0; q < 8; q++) {
    float2 f = unpack2(acc[q]);
    op[2*q+0] = fmaxf(fmaf(f.x, sc, bi), 0.f);
    op[2*q+1] = fmaxf(fmaf(f.y, sc, bi), 0.f);
  }
}

// ------- 3x3 conv: offset/mask (216 ch), f32x2 o-pairs, 32-px tiles ---------
// Block: 224 threads, t<216 compute (o-pair, px-half of 16). Channels chunked
// by 32 through a 26 KB duplicated halo buffer. 1024 blocks.
__global__ void __launch_bounds__(224, 3) k_om(const float* __restrict__ b_om) {
  __shared__ u64 xs[32 * 102];               // [c][3 kh][34 cols] dup, 26112 B
  int bid = blockIdx.x;                      // 1024 = b(8) x h(64) x wq(2)
  int b = bid >> 7; int rem = bid & 127;
  int h = rem >> 1; int wb = (rem & 1) << 5;
  int t = threadIdx.x;
  int op2 = t >> 1;                          // output pair 0..107
  int ph  = t & 1;                           // pixel half (16 px)
  u64 acc[16];
#pragma unroll
  for (int p = 0; p < 16; p++) acc[p] = 0ull;
  const float* wbase = g_womt + op2 * 2;

  for (int cb = 0; cb < 4; cb++) {
    for (int i = t; i < 32 * 102; i += 224) {
      int c = i / 102; int r = i - c * 102; int kh = r / 34; int col = r - kh * 34;
      int hh = h + kh - 1; int ww = wb + col - 1;
      float v = 0.f;
      if ((unsigned)hh < 64u && (unsigned)ww < 64u)
        v = g_off[((size_t)(b * 128 + cb * 32 + c)) * 4096 + hh * 64 + ww];
      xs[i] = pack2(v, v);
    }
    __syncthreads();
    if (t < 216) {
      for (int c = 0; c < 32; c++) {
        const float* wc = wbase + ((cb * 32 + c) * 9) * 216;
        const u64* xc = xs + c * 102 + ph * 16;
#pragma unroll
        for (int kh = 0; kh < 3; kh++) {
          u64 w0 = *(const u64*)(wc + (kh * 3 + 0) * 216);
          u64 w1 = *(const u64*)(wc + (kh * 3 + 1) * 216);
          u64 w2 = *(const u64*)(wc + (kh * 3 + 2) * 216);
          const u64* xr = xc + kh * 34;
          u64 a0 = xr[0], a1 = xr[1];
#pragma unroll
          for (int j = 0; j < 16; j++) {
            u64 a2 = xr[j + 2];
            acc[j] = fma2(w0, a0, acc[j]);
            acc[j] = fma2(w1, a1, acc[j]);
            acc[j] = fma2(w2, a2, acc[j]);
            a0 = a1; a1 = a2;
          }
        }
      }
    }
    __syncthreads();
  }
  if (t < 216) {
    int o0 = op2 * 2;
    float bo0 = b_om[o0], bo1 = b_om[o0 + 1];
    float* p0 = g_om + ((size_t)(b * 216 + o0)) * 4096 + h * 64 + wb + ph * 16;
    float* p1 = p0 + 4096;
#pragma unroll
    for (int j = 0; j < 16; j++) {
      float2 f = unpack2(acc[j]);
      p0[j] = f.x + bo0;
      p1[j] = f.y + bo1;
    }
  }
}

// ---------------- modulated deformable conv + relu (R2 version) -------------
__global__ void __launch_bounds__(256) k_dcn(const float* __restrict__ b_dcn) {
  extern __shared__ float sm[];
  float* pw   = sm;                       // [16 px][72 gk][4 corners] weights
  int*   pidx = (int*)(sm + 4608);        // matching channel-base offsets
  float* val  = sm + 9216;                // [16 px][1152 e], e = k*128 + cc
  int bid = blockIdx.x;                   // 2048 blocks
  int b = bid >> 8; int rem = bid & 255;
  int h = rem >> 2; int wb = (rem & 3) << 4;
  const float* omb = g_om + (size_t)b * 216 * 4096 + h * 64 + wb;

  // phase 0: per-(pixel,g,k) bilinear params (mask folded into weights)
  for (int i = threadIdx.x; i < 1152; i += 256) {
    int p = i / 72; int r = i - p * 72; int g = r / 9; int k = r - g * 9;
    int wq = wb + p;
    float oy = omb[(g * 9 + k) * 4096 + p];
    float ox = omb[(72 + g * 9 + k) * 4096 + p];
    float mr = omb[(144 + g * 9 + k) * 4096 + p];
    float m = 1.0f / (1.0f + expf(-mr));
    float py = (float)(h + k / 3 - 1) + oy;
    float px = (float)(wq + k % 3 - 1) + ox;
    float y0 = floorf(py), x0 = floorf(px);
    float ty = py - y0, tx = px - x0;
    int iy0 = (int)y0, ix0 = (int)x0;
#pragma unroll
    for (int j = 0; j < 4; j++) {
      int iy = iy0 + (j >> 1), ix = ix0 + (j & 1);
      bool v = (iy >= 0) && (iy < 64) && (ix >= 0) && (ix < 64);
      float wy = (j >> 1) ? ty : 1.0f - ty;
      float wx = (j & 1) ? tx : 1.0f - tx;
      pw[i * 4 + j]   = v ? wy * wx * m : 0.0f;
      pidx[i * 4 + j] = v ? (((iy >> 1) * 32 + (ix >> 1)) * 128) : 0;
    }
  }
  __syncthreads();

  // phase 1: bilinear gathers from NHWC feat_s -> val, float4 over channels
  const float* fsb = g_fsn + (size_t)b * 1024 * 128;
  for (int ei = threadIdx.x; ei < 4608; ei += 256) {
    int p = ei / 288; int r = ei - p * 288;
    int k = r >> 5; int cc4 = r & 31; int g = cc4 >> 2;
    int slot = (p * 72 + g * 9 + k) * 4;
    float4 a = make_float4(0.f, 0.f, 0.f, 0.f);
#pragma unroll
    for (int j = 0; j < 4; j++) {
      float w = pw[slot + j];
      const float4 v = *(const float4*)(fsb + pidx[slot + j] + cc4 * 4);
      a.x = fmaf(w, v.x, a.x);
      a.y = fmaf(w, v.y, a.y);
      a.z = fmaf(w, v.z, a.z);
      a.w = fmaf(w, v.w, a.w);
    }
    *(float4*)(val + p * 1152 + k * 128 + cc4 * 4) = a;
  }
  __syncthreads();

  // phase 2: out[o] = relu(b + sum_e Wdcn_t[e][o] * val[p][e]), 4 px/thread
  int o  = threadIdx.x & 63;
  int ps = threadIdx.x >> 6;
  const float4* w4 = (const float4*)g_wdt;        // [288][64] of float4
  const float4* v0 = (const float4*)(val + (ps * 4 + 0) * 1152);
  const float4* v1 = (const float4*)(val + (ps * 4 + 1) * 1152);
  const float4* v2 = (const float4*)(val + (ps * 4 + 2) * 1152);
  const float4* v3 = (const float4*)(val + (ps * 4 + 3) * 1152);
  float a0 = 0.f, a1 = 0.f, a2 = 0.f, a3 = 0.f;
  for (int eq = 0; eq < 288; eq++) {
    float4 w = w4[eq * 64 + o];
    float4 x0 = v0[eq], x1 = v1[eq], x2 = v2[eq], x3 = v3[eq];
    a0 = fmaf(w.x, x0.x, a0); a0 = fmaf(w.y, x0.y, a0);
    a0 = fmaf(w.z, x0.z, a0); a0 = fmaf(w.w, x0.w, a0);
    a1 = fmaf(w.x, x1.x, a1); a1 = fmaf(w.y, x1.y, a1);
    a1 = fmaf(w.z, x1.z, a1); a1 = fmaf(w.w, x1.w, a1);
    a2 = fmaf(w.x, x2.x, a2); a2 = fmaf(w.y, x2.y, a2);
    a2 = fmaf(w.z, x2.z, a2); a2 = fmaf(w.w, x2.w, a2);
    a3 = fmaf(w.x, x3.x, a3); a3 = fmaf(w.y, x3.y, a3);
    a3 = fmaf(w.z, x3.z, a3); a3 = fmaf(w.w, x3.w, a3);
  }
  float bo = b_dcn[o];
  float4 r;
  r.x = fmaxf(a0 + bo, 0.f);
  r.y = fmaxf(a1 + bo, 0.f);
  r.z = fmaxf(a2 + bo, 0.f);
  r.w = fmaxf(a3 + bo, 0.f);
  *(float4*)(g_align + ((size_t)(b * 64 + o)) * 4096 + h * 64 + wb + ps * 4) = r;
}

// ---------------- final 1x1 conv + BN + relu + residual (f32x2) -------------
__global__ void __launch_bounds__(256) k_cat(
    const float* __restrict__ s, const float* __restrict__ bias,
    const float* __restrict__ arm, float* __restrict__ out) {
  __shared__ float xs[64 * 64];              // 16 KB
  int b = blockIdx.x >> 6;
  int pbase = (blockIdx.x & 63) * 64;
  for (int i = threadIdx.x; i < 4096; i += 256)
    xs[i] = g_align[((size_t)(b * 64 + (i >> 6))) * 4096 + pbase + (i & 63)];
  __syncthreads();
  int o  = threadIdx.x & 127;
  int ph = threadIdx.x >> 7;
  u64 acc[16];
#pragma unroll
  for (int p = 0; p < 16; p++) acc[p] = 0ull;
  for (int c = 0; c < 64; c++) {
    float w = g_wt_cat[c * 128 + o];
    u64 wd = pack2(w, w);
    const ulonglong2* xr = (const ulonglong2*)(xs + c * 64 + ph * 32);
#pragma unroll
    for (int q = 0; q < 8; q++) {
      ulonglong2 v = xr[q];
      acc[2*q+0] = fma2(wd, v.x, acc[2*q+0]);
      acc[2*q+1] = fma2(wd, v.y, acc[2*q+1]);
    }
  }
  float sc = s[o], bi = bias[o];
  size_t base = ((size_t)(b * 128 + o)) * 4096 + pbase + ph * 32;
#pragma unroll
  for (int q = 0; q < 16; q++) {
    float2 f = unpack2(acc[q]);
    out[base + 2*q+0] = fmaxf(fmaf(f.x, sc, bi), 0.f) + arm[base + 2*q+0];
    out[base + 2*q+1] = fmaxf(fmaf(f.y, sc, bi), 0.f) + arm[base + 2*q+1];
  }
}

// ---------------- launcher ---------------------------------------------------
extern "C" void kernel_launch(void* const* d_in, const int* in_sizes, int n_in,
                              void* d_out, int out_size) {
  const float* feat_l = (const float*)d_in[0];
  const float* feat_s = (const float*)d_in[1];
  const float* W_fsm  = (const float*)d_in[2];
  const float* s_fsm  = (const float*)d_in[3];
  const float* b_fsm  = (const float*)d_in[4];
  const float* W_off  = (const float*)d_in[5];
  const float* s_off  = (const float*)d_in[6];
  const float* b_off  = (const float*)d_in[7];
  const float* W_om   = (const float*)d_in[8];
  const float* b_om   = (const float*)d_in[9];
  const float* W_dcn  = (const float*)d_in[10];
  const float* b_dcn  = (const float*)d_in[11];
  const float* W_cat  = (const float*)d_in[12];
  const float* s_cat  = (const float*)d_in[13];
  const float* b_cat  = (const float*)d_in[14];

  float* out_feat = (float*)d_out;
  float* out_arm  = out_feat + (size_t)8 * 128 * 4096;   // second tuple element

  cudaFuncSetAttribute(k_dcn, cudaFuncAttributeMaxDynamicSharedMemorySize, 110592);

  k_prep<<<4096, 256>>>(feat_s, W_fsm, W_off, W_cat, W_om, W_dcn);
  k_fsm <<<512, 256>>>(feat_l, s_fsm, b_fsm, out_arm);
  k_off <<<1024, 256>>>(out_arm, feat_s, s_off, b_off);
  k_om  <<<1024, 224>>>(b_om);
  k_dcn <<<2048, 256, 110592>>>(b_dcn);
  k_cat <<<512, 256>>>(s_cat, b_cat, out_arm, out_feat);
}

// round 7
// speedup vs baseline: 1.0628x; 1.0626x over previous
#include <cuda_runtime.h>
#include <cuda_bf16.h>
#include <math.h>

typedef unsigned long long u64;

__device__ __forceinline__ u64 pack2(float x, float y) {
  u64 r; asm("mov.b64 %0,{%1,%2};" : "=l"(r) : "f"(x), "f"(y)); return r;
}
__device__ __forceinline__ u64 fma2(u64 a, u64 b, u64 c) {
  u64 d; asm("fma.rn.f32x2 %0,%1,%2,%3;" : "=l"(d) : "l"(a), "l"(b), "l"(c)); return d;
}
__device__ __forceinline__ float2 unpack2(u64 v) {
  float2 f; asm("mov.b64 {%0,%1},%2;" : "=f"(f.x), "=f"(f.y) : "l"(v)); return f;
}

// ---------------- scratch (device globals; no cudaMalloc allowed) ----------
__device__ float g_off [8 * 128 * 4096];   // offset features (after 1x1 conv)
__device__ float g_om  [8 * 216 * 4096];   // 3x3 conv output (off_y/off_x/mask raw)
__device__ float g_fsn [8 * 1024 * 128];   // feat_s transposed to [b][sp][c] (NHWC)
__device__ float g_align[8 * 64 * 4096];   // DCN output after relu
__device__ float g_wdt [288 * 64 * 4];     // W_dcn repacked: [(e>>2)][o][e&3], e = k*128+cc
__device__ float g_womt[129 * 9 * 216];    // W_om repacked: [(c*9+t)][o]; +1 ch pad for prefetch
__device__ float g_wt_fsm[128 * 128];      // W_fsm^T : [c][o]
__device__ float g_wt_off[256 * 128];      // W_off^T : [c][o]
__device__ float g_wt_cat[64 * 128];       // W_cat^T : [c][o]

// ---------------- prep: transposes / repacks --------------------------------
__global__ void __launch_bounds__(256) k_prep(
    const float* __restrict__ fs, const float* __restrict__ W_fsm,
    const float* __restrict__ W_off, const float* __restrict__ W_cat,
    const float* __restrict__ W_om, const float* __restrict__ W_dcn) {
  int i = blockIdx.x * 256 + threadIdx.x;   // grid covers 1048576
  if (i < 1048576) {   // feat_s NCHW -> [b][sp][c]
    int b = i >> 17; int r = i & 131071; int c = r >> 10; int sp = r & 1023;
    g_fsn[((b << 10) + sp) * 128 + c] = fs[i];
  }
  if (i < 16384) g_wt_fsm[(i & 127) * 128 + (i >> 7)] = W_fsm[i];   // i = o*128+c
  if (i < 32768) g_wt_off[(i & 255) * 128 + (i >> 8)] = W_off[i];   // i = o*256+c
  if (i < 8192)  g_wt_cat[(i & 63)  * 128 + (i >> 6)] = W_cat[i];   // i = o*64+c
  if (i < 248832) {            // W_om: i = o*1152 + (c*9+t)
    int o = i / 1152; int r = i - o * 1152;
    g_womt[r * 216 + o] = W_om[i];
  }
  if (i < 73728) {             // W_dcn: i = o*1152 + cc*9 + k
    int o = i / 1152; int r = i - o * 1152; int cc = r / 9; int k = r - cc * 9;
    int e = k * 128 + cc;
    g_wdt[(e >> 2) * 256 + o * 4 + (e & 3)] = W_dcn[i];
  }
}

// ---------------- 1x1 conv + BN + relu : feat_arm (f32x2 over pixel pairs) --
__global__ void __launch_bounds__(256) k_fsm(
    const float* __restrict__ x, const float* __restrict__ s,
    const float* __restrict__ bias, float* __restrict__ arm) {
  __shared__ float xs[128 * 64];            // 32 KB input tile
  int b = blockIdx.x >> 6;
  int pbase = (blockIdx.x & 63) * 64;
  const float* xb = x + ((size_t)b * 128) * 4096 + pbase;
  for (int i = threadIdx.x; i < 128 * 64; i += 256)
    xs[i] = xb[(size_t)(i >> 6) * 4096 + (i & 63)];
  __syncthreads();
  int o  = threadIdx.x & 127;
  int ph = threadIdx.x >> 7;                // pixel half: 32 px each
  u64 acc[16];
#pragma unroll
  for (int p = 0; p < 16; p++) acc[p] = 0ull;
  for (int c = 0; c < 128; c++) {
    float w = g_wt_fsm[c * 128 + o];
    u64 wd = pack2(w, w);
    const ulonglong2* xr = (const ulonglong2*)(xs + c * 64 + ph * 32);
#pragma unroll
    for (int q = 0; q < 8; q++) {
      ulonglong2 v = xr[q];
      acc[2*q+0] = fma2(wd, v.x, acc[2*q+0]);
      acc[2*q+1] = fma2(wd, v.y, acc[2*q+1]);
    }
  }
  float sc = s[o], bi = bias[o];
  float* op = arm + ((size_t)(b * 128 + o)) * 4096 + pbase + ph * 32;
#pragma unroll
  for (int q = 0; q < 16; q++) {
    float2 f = unpack2(acc[q]);
    op[2*q+0] = fmaxf(fmaf(f.x, sc, bi), 0.f);
    op[2*q+1] = fmaxf(fmaf(f.y, sc, bi), 0.f);
  }
}

// ------------- 1x1 conv over concat(arm, 2*upsample(feat_s)) (f32x2) --------
__global__ void __launch_bounds__(256) k_off(
    const float* __restrict__ arm, const float* __restrict__ fs,
    const float* __restrict__ s, const float* __restrict__ bias) {
  __shared__ float xs1[128 * 32];
  __shared__ float xs2[128 * 32];
  int bid = blockIdx.x;                      // 1024 blocks
  int b = bid >> 7; int rem = bid & 127;
  int h = rem >> 1; int wb = (rem & 1) << 5;
  for (int i = threadIdx.x; i < 4096; i += 256) {
    int c = i >> 5; int p = i & 31;
    xs1[i] = arm[((size_t)(b * 128 + c)) * 4096 + h * 64 + wb + p];
    xs2[i] = 2.0f * fs[((size_t)(b * 128 + c)) * 1024 + (h >> 1) * 32 + ((wb + p) >> 1)];
  }
  __syncthreads();
  int o  = threadIdx.x & 127;
  int ph = threadIdx.x >> 7;                 // 16 px each
  u64 acc[8];
#pragma unroll
  for (int p = 0; p < 8; p++) acc[p] = 0ull;
  for (int c = 0; c < 128; c++) {
    float w = g_wt_off[c * 128 + o];
    u64 wd = pack2(w, w);
    const ulonglong2* xr = (const ulonglong2*)(xs1 + c * 32 + ph * 16);
#pragma unroll
    for (int q = 0; q < 4; q++) {
      ulonglong2 v = xr[q];
      acc[2*q+0] = fma2(wd, v.x, acc[2*q+0]);
      acc[2*q+1] = fma2(wd, v.y, acc[2*q+1]);
    }
  }
  for (int c = 0; c < 128; c++) {
    float w = g_wt_off[(128 + c) * 128 + o];
    u64 wd = pack2(w, w);
    const ulonglong2* xr = (const ulonglong2*)(xs2 + c * 32 + ph * 16);
#pragma unroll
    for (int q = 0; q < 4; q++) {
      ulonglong2 v = xr[q];
      acc[2*q+0] = fma2(wd, v.x, acc[2*q+0]);
      acc[2*q+1] = fma2(wd, v.y, acc[2*q+1]);
    }
  }
  float sc = s[o], bi = bias[o];
  float* op = g_off + ((size_t)(b * 128 + o)) * 4096 + h * 64 + wb + ph * 16;
#pragma unroll
  for (int q = 0; q < 8; q++) {
    float2 f = unpack2(acc[q]);
    op[2*q+0] = fmaxf(fmaf(f.x, sc, bi), 0.f);
    op[2*q+1] = fmaxf(fmaf(f.y, sc, bi), 0.f);
  }
}

// ------- 3x3 conv helpers: weight prefetch + fma block ----------------------
__device__ __forceinline__ void om_wload(u64 w[9], const float* wc) {
#pragma unroll
  for (int q = 0; q < 9; q++) w[q] = *(const u64*)(wc + q * 216);
}
__device__ __forceinline__ void om_fma(u64 acc[8], const u64* xc, const u64 w[9]) {
#pragma unroll
  for (int kh = 0; kh < 3; kh++) {
    const u64* xr = xc + kh * 18;
    u64 a0 = xr[0], a1 = xr[1];
#pragma unroll
    for (int j = 0; j < 8; j++) {
      u64 a2 = xr[j + 2];
      acc[j] = fma2(w[kh*3+0], a0, acc[j]);
      acc[j] = fma2(w[kh*3+1], a1, acc[j]);
      acc[j] = fma2(w[kh*3+2], a2, acc[j]);
      a0 = a1; a1 = a2;
    }
  }
}

// ------- 3x3 conv: offset/mask (216 ch), f32x2 o-pairs, 16-px tiles ---------
// 2x64 channel chunks (27.6 KB halo), double-buffered register weight prefetch.
__global__ void __launch_bounds__(256, 3) k_om(const float* __restrict__ b_om) {
  __shared__ u64 xs[64 * 54];                // [c][3 kh][18 cols] dup, 27648 B
  int bid = blockIdx.x;                      // 2048 = b(8) x h(64) x wq(4)
  int b = bid >> 8; int rem = bid & 255;
  int h = rem >> 2; int wb = (rem & 3) << 4;
  int t = threadIdx.x;
  int op2 = t >> 1;                          // output pair 0..107
  int ph  = t & 1;                           // pixel half (8 px)
  u64 acc[8];
#pragma unroll
  for (int p = 0; p < 8; p++) acc[p] = 0ull;
  const float* wp = g_womt + op2 * 2;        // channel-0 weights for this o-pair

  u64 wA[9], wB[9];
  if (t < 216) om_wload(wA, wp);             // prefetch channel 0

  for (int cb = 0; cb < 2; cb++) {
    for (int i = t; i < 64 * 54; i += 256) {
      int c = i / 54; int r = i - c * 54; int kh = r / 18; int col = r - kh * 18;
      int hh = h + kh - 1; int ww = wb + col - 1;
      float v = 0.f;
      if ((unsigned)hh < 64u && (unsigned)ww < 64u)
        v = g_off[((size_t)(b * 128 + cb * 64 + c)) * 4096 + hh * 64 + ww];
      xs[i] = pack2(v, v);
    }
    __syncthreads();
    if (t < 216) {
      for (int c = 0; c < 64; c += 2) {
        int cg = cb * 64 + c;
        om_wload(wB, wp + (size_t)(cg + 1) * 9 * 216);   // prefetch c+1
        om_fma(acc, xs + c * 54 + ph * 8, wA);           // compute c
        om_wload(wA, wp + (size_t)(cg + 2) * 9 * 216);   // prefetch c+2 (pad at 128)
        om_fma(acc, xs + (c + 1) * 54 + ph * 8, wB);     // compute c+1
      }
    }
    __syncthreads();
  }
  if (t < 216) {
    int o0 = op2 * 2;
    float bo0 = b_om[o0], bo1 = b_om[o0 + 1];
    float* p0 = g_om + ((size_t)(b * 216 + o0)) * 4096 + h * 64 + wb + ph * 8;
    float* p1 = p0 + 4096;
#pragma unroll
    for (int j = 0; j < 8; j++) {
      float2 f = unpack2(acc[j]);
      p0[j] = f.x + bo0;
      p1[j] = f.y + bo1;
    }
  }
}

// ---------------- modulated deformable conv + relu (R2 version) -------------
__global__ void __launch_bounds__(256) k_dcn(const float* __restrict__ b_dcn) {
  extern __shared__ float sm[];
  float* pw   = sm;                       // [16 px][72 gk][4 corners] weights
  int*   pidx = (int*)(sm + 4608);        // matching channel-base offsets
  float* val  = sm + 9216;                // [16 px][1152 e], e = k*128 + cc
  int bid = blockIdx.x;                   // 2048 blocks
  int b = bid >> 8; int rem = bid & 255;
  int h = rem >> 2; int wb = (rem & 3) << 4;
  const float* omb = g_om + (size_t)b * 216 * 4096 + h * 64 + wb;

  // phase 0: per-(pixel,g,k) bilinear params (mask folded into weights)
  for (int i = threadIdx.x; i < 1152; i += 256) {
    int p = i / 72; int r = i - p * 72; int g = r / 9; int k = r - g * 9;
    int wq = wb + p;
    float oy = omb[(g * 9 + k) * 4096 + p];
    float ox = omb[(72 + g * 9 + k) * 4096 + p];
    float mr = omb[(144 + g * 9 + k) * 4096 + p];
    float m = 1.0f / (1.0f + expf(-mr));
    float py = (float)(h + k / 3 - 1) + oy;
    float px = (float)(wq + k % 3 - 1) + ox;
    float y0 = floorf(py), x0 = floorf(px);
    float ty = py - y0, tx = px - x0;
    int iy0 = (int)y0, ix0 = (int)x0;
#pragma unroll
    for (int j = 0; j < 4; j++) {
      int iy = iy0 + (j >> 1), ix = ix0 + (j & 1);
      bool v = (iy >= 0) && (iy < 64) && (ix >= 0) && (ix < 64);
      float wy = (j >> 1) ? ty : 1.0f - ty;
      float wx = (j & 1) ? tx : 1.0f - tx;
      pw[i * 4 + j]   = v ? wy * wx * m : 0.0f;
      pidx[i * 4 + j] = v ? (((iy >> 1) * 32 + (ix >> 1)) * 128) : 0;
    }
  }
  __syncthreads();

  // phase 1: bilinear gathers from NHWC feat_s -> val, float4 over channels
  const float* fsb = g_fsn + (size_t)b * 1024 * 128;
  for (int ei = threadIdx.x; ei < 4608; ei += 256) {
    int p = ei / 288; int r = ei - p * 288;
    int k = r >> 5; int cc4 = r & 31; int g = cc4 >> 2;
    int slot = (p * 72 + g * 9 + k) * 4;
    float4 a = make_float4(0.f, 0.f, 0.f, 0.f);
#pragma unroll
    for (int j = 0; j < 4; j++) {
      float w = pw[slot + j];
      const float4 v = *(const float4*)(fsb + pidx[slot + j] + cc4 * 4);
      a.x = fmaf(w, v.x, a.x);
      a.y = fmaf(w, v.y, a.y);
      a.z = fmaf(w, v.z, a.z);
      a.w = fmaf(w, v.w, a.w);
    }
    *(float4*)(val + p * 1152 + k * 128 + cc4 * 4) = a;
  }
  __syncthreads();

  // phase 2: out[o] = relu(b + sum_e Wdcn_t[e][o] * val[p][e]), 4 px/thread
  int o  = threadIdx.x & 63;
  int ps = threadIdx.x >> 6;
  const float4* w4 = (const float4*)g_wdt;        // [288][64] of float4
  const float4* v0 = (const float4*)(val + (ps * 4 + 0) * 1152);
  const float4* v1 = (const float4*)(val + (ps * 4 + 1) * 1152);
  const float4* v2 = (const float4*)(val + (ps * 4 + 2) * 1152);
  const float4* v3 = (const float4*)(val + (ps * 4 + 3) * 1152);
  float a0 = 0.f, a1 = 0.f, a2 = 0.f, a3 = 0.f;
  for (int eq = 0; eq < 288; eq++) {
    float4 w = w4[eq * 64 + o];
    float4 x0 = v0[eq], x1 = v1[eq], x2 = v2[eq], x3 = v3[eq];
    a0 = fmaf(w.x, x0.x, a0); a0 = fmaf(w.y, x0.y, a0);
    a0 = fmaf(w.z, x0.z, a0); a0 = fmaf(w.w, x0.w, a0);
    a1 = fmaf(w.x, x1.x, a1); a1 = fmaf(w.y, x1.y, a1);
    a1 = fmaf(w.z, x1.z, a1); a1 = fmaf(w.w, x1.w, a1);
    a2 = fmaf(w.x, x2.x, a2); a2 = fmaf(w.y, x2.y, a2);
    a2 = fmaf(w.z, x2.z, a2); a2 = fmaf(w.w, x2.w, a2);
    a3 = fmaf(w.x, x3.x, a3); a3 = fmaf(w.y, x3.y, a3);
    a3 = fmaf(w.z, x3.z, a3); a3 = fmaf(w.w, x3.w, a3);
  }
  float bo = b_dcn[o];
  float4 r;
  r.x = fmaxf(a0 + bo, 0.f);
  r.y = fmaxf(a1 + bo, 0.f);
  r.z = fmaxf(a2 + bo, 0.f);
  r.w = fmaxf(a3 + bo, 0.f);
  *(float4*)(g_align + ((size_t)(b * 64 + o)) * 4096 + h * 64 + wb + ps * 4) = r;
}

// ---------------- final 1x1 conv + BN + relu + residual (f32x2) -------------
__global__ void __launch_bounds__(256) k_cat(
    const float* __restrict__ s, const float* __restrict__ bias,
    const float* __restrict__ arm, float* __restrict__ out) {
  __shared__ float xs[64 * 64];              // 16 KB
  int b = blockIdx.x >> 6;
  int pbase = (blockIdx.x & 63) * 64;
  for (int i = threadIdx.x; i < 4096; i += 256)
    xs[i] = g_align[((size_t)(b * 64 + (i >> 6))) * 4096 + pbase + (i & 63)];
  __syncthreads();
  int o  = threadIdx.x & 127;
  int ph = threadIdx.x >> 7;
  u64 acc[16];
#pragma unroll
  for (int p = 0; p < 16; p++) acc[p] = 0ull;
  for (int c = 0; c < 64; c++) {
    float w = g_wt_cat[c * 128 + o];
    u64 wd = pack2(w, w);
    const ulonglong2* xr = (const ulonglong2*)(xs + c * 64 + ph * 32);
#pragma unroll
    for (int q = 0; q < 8; q++) {
      ulonglong2 v = xr[q];
      acc[2*q+0] = fma2(wd, v.x, acc[2*q+0]);
      acc[2*q+1] = fma2(wd, v.y, acc[2*q+1]);
    }
  }
  float sc = s[o], bi = bias[o];
  size_t base = ((size_t)(b * 128 + o)) * 4096 + pbase + ph * 32;
#pragma unroll
  for (int q = 0; q < 16; q++) {
    float2 f = unpack2(acc[q]);
    out[base + 2*q+0] = fmaxf(fmaf(f.x, sc, bi), 0.f) + arm[base + 2*q+0];
    out[base + 2*q+1] = fmaxf(fmaf(f.y, sc, bi), 0.f) + arm[base + 2*q+1];
  }
}

// ---------------- launcher ---------------------------------------------------
extern "C" void kernel_launch(void* const* d_in, const int* in_sizes, int n_in,
                              void* d_out, int out_size) {
  const float* feat_l = (const float*)d_in[0];
  const float* feat_s = (const float*)d_in[1];
  const float* W_fsm  = (const float*)d_in[2];
  const float* s_fsm  = (const float*)d_in[3];
  const float* b_fsm  = (const float*)d_in[4];
  const float* W_off  = (const float*)d_in[5];
  const float* s_off  = (const float*)d_in[6];
  const float* b_off  = (const float*)d_in[7];
  const float* W_om   = (const float*)d_in[8];
  const float* b_om   = (const float*)d_in[9];
  const float* W_dcn  = (const float*)d_in[10];
  const float* b_dcn  = (const float*)d_in[11];
  const float* W_cat  = (const float*)d_in[12];
  const float* s_cat  = (const float*)d_in[13];
  const float* b_cat  = (const float*)d_in[14];

  float* out_feat = (float*)d_out;
  float* out_arm  = out_feat + (size_t)8 * 128 * 4096;   // second tuple element

  cudaFuncSetAttribute(k_dcn, cudaFuncAttributeMaxDynamicSharedMemorySize, 110592);

  k_prep<<<4096, 256>>>(feat_s, W_fsm, W_off, W_cat, W_om, W_dcn);
  k_fsm <<<512, 256>>>(feat_l, s_fsm, b_fsm, out_arm);
  k_off <<<1024, 256>>>(out_arm, feat_s, s_off, b_off);
  k_om  <<<2048, 256>>>(b_om);
  k_dcn <<<2048, 256, 110592>>>(b_dcn);
  k_cat <<<512, 256>>>(s_cat, b_cat, out_arm, out_feat);
}